// round 1
// baseline (speedup 1.0000x reference)
#include <cuda_runtime.h>
#include <math_constants.h>
#include <cstdint>

// Problem constants (fixed shapes)
#define B_  8
#define N_  4096
#define D_  128
#define C_  256
#define K_  16

// ---------------- scratch (device globals; allocation-free rule) -------------
__device__ float g_M[D_ * D_];            // WqT * Wk
__device__ float g_v[D_];                 // bq * Wk
__device__ int   g_idx[B_ * N_ * K_];     // knn indices
__device__ float g_qt[(size_t)B_ * N_ * D_];   // folded query
__device__ float g_Ft[(size_t)B_ * N_ * C_];   // transposed fp4 features [B,N,C]

// ---------------- K0: fold weights ------------------------------------------
// M[c,d] = sum_e Wq[e,c] * Wk[e,d];  v[d] = sum_e bq[e] * Wk[e,d]
__global__ void fold_kernel(const float* __restrict__ Wq,
                            const float* __restrict__ Wk,
                            const float* __restrict__ bq) {
    int c = blockIdx.x;      // 0..127
    int d = threadIdx.x;     // 0..127
    float acc = 0.f;
#pragma unroll 8
    for (int e = 0; e < D_; e++)
        acc = fmaf(Wq[e * D_ + c], Wk[e * D_ + d], acc);
    g_M[c * D_ + d] = acc;
    if (c == 0) {
        float a2 = 0.f;
#pragma unroll 8
        for (int e = 0; e < D_; e++)
            a2 = fmaf(bq[e], Wk[e * D_ + d], a2);
        g_v[d] = a2;
    }
}

// ---------------- K1: KNN (top-16 by pd = 2*inner - xxq - xxc) ---------------
// One thread per query point; whole batch xyz (+|x|^2) staged in 64KB smem.
__global__ __launch_bounds__(128) void knn_kernel(const float* __restrict__ xyz) {
    extern __shared__ float4 spts[];            // [N_] (x,y,z,xx) = 64KB dynamic
    const int b = blockIdx.y;
    const float* base = xyz + (size_t)b * N_ * 3;

    for (int j = threadIdx.x; j < N_; j += blockDim.x) {
        float x = base[j * 3 + 0];
        float y = base[j * 3 + 1];
        float z = base[j * 3 + 2];
        float xx = fmaf(x, x, fmaf(y, y, z * z));
        spts[j] = make_float4(x, y, z, xx);
    }
    __syncthreads();

    const int n = blockIdx.x * blockDim.x + threadIdx.x;
    const float4 q = spts[n];

    float vbest[K_];
    int   ibest[K_];
#pragma unroll
    for (int t = 0; t < K_; t++) { vbest[t] = -CUDART_INF_F; ibest[t] = 0; }
    float vmin = -CUDART_INF_F;
    int   minslot = 0;

#pragma unroll 4
    for (int j = 0; j < N_; j++) {
        float4 c = spts[j];
        float inner = fmaf(q.x, c.x, fmaf(q.y, c.y, q.z * c.z));
        float pd = fmaf(2.f, inner, -q.w) - c.w;
        if (pd > vmin) {
            // replace current min slot (compile-time indices only -> stays in regs)
#pragma unroll
            for (int t = 0; t < K_; t++)
                if (t == minslot) { vbest[t] = pd; ibest[t] = j; }
            // rescan for new min
            vmin = vbest[0]; minslot = 0;
#pragma unroll
            for (int t = 1; t < K_; t++)
                if (vbest[t] < vmin) { vmin = vbest[t]; minslot = t; }
        }
    }

    int* out = g_idx + ((size_t)b * N_ + n) * K_;
#pragma unroll
    for (int t = 0; t < K_; t++) out[t] = ibest[t];
}

// ---------------- K2: qt = X @ M + v  ([B*N,128]x[128,128]) ------------------
// Warp per output row. M staged in 64KB dynamic smem; X row held strided in
// registers and broadcast via shfl; M rows read as conflict-free LDS.128.
__global__ __launch_bounds__(1024) void qt_kernel(const float* __restrict__ X) {
    extern __shared__ float Ms[];               // 128*128 floats = 64KB
    const int tid = threadIdx.x;
    for (int i = tid; i < D_ * D_; i += 1024) Ms[i] = g_M[i];
    __syncthreads();

    const int warp = tid >> 5, lane = tid & 31;
    const int row = blockIdx.x * 32 + warp;     // 1024 blocks * 32 rows = 32768

    const float* Xr = X + (size_t)row * D_;
    float xr[4];
#pragma unroll
    for (int t = 0; t < 4; t++) xr[t] = Xr[lane + 32 * t];

    const float4* Ms4 = (const float4*)Ms;
    float4 acc = ((const float4*)g_v)[lane];    // out cols d = 4*lane..4*lane+3

#pragma unroll
    for (int t = 0; t < 4; t++) {
#pragma unroll
        for (int l = 0; l < 32; l++) {
            float xc = __shfl_sync(0xffffffffu, xr[t], l);
            float4 m = Ms4[(t * 32 + l) * 32 + lane];
            acc.x = fmaf(xc, m.x, acc.x);
            acc.y = fmaf(xc, m.y, acc.y);
            acc.z = fmaf(xc, m.z, acc.z);
            acc.w = fmaf(xc, m.w, acc.w);
        }
    }
    ((float4*)g_qt)[(size_t)row * 32 + lane] = acc;
}

// ---------------- K3: transpose fp4_features [B,C,N] -> [B,N,C] --------------
__global__ void transpose_kernel(const float* __restrict__ F) {
    __shared__ float t[32][33];
    const int b = blockIdx.z;
    const int n0 = blockIdx.x * 32, c0 = blockIdx.y * 32;
    const int tx = threadIdx.x, ty = threadIdx.y;
    const float* Fb = F + (size_t)b * C_ * N_;
#pragma unroll
    for (int i = 0; i < 4; i++)
        t[ty + 8 * i][tx] = Fb[(size_t)(c0 + ty + 8 * i) * N_ + n0 + tx];
    __syncthreads();
    float* Ftb = g_Ft + (size_t)b * N_ * C_;
#pragma unroll
    for (int i = 0; i < 4; i++)
        Ftb[(size_t)(n0 + ty + 8 * i) * C_ + c0 + tx] = t[tx][ty + 8 * i];
}

// ---------------- K4: scores + softmax + weighted gather + coalesced out -----
// Warp per point (32 points/block). scores_k = (qt . X[j_k]) / sqrt(D).
// out[b,c,n] = sum_k a_k * Ft[b,j_k,c], staged in smem, written coalesced.
__global__ __launch_bounds__(1024) void attn_kernel(const float* __restrict__ X,
                                                    float* __restrict__ out) {
    __shared__ float tile[C_ * 33];             // [c][n_local], pad 33 -> 33.8KB

    const int w = threadIdx.x >> 5, lane = threadIdx.x & 31;
    const int b = blockIdx.y;
    const int n0 = blockIdx.x * 32;
    const int n = n0 + w;
    const size_t pt = (size_t)b * N_ + n;

    const float4 q = ((const float4*)g_qt)[pt * 32 + lane];
    int jlane = (lane < K_) ? g_idx[pt * K_ + lane] : 0;

    const float4* Xv = (const float4*)X + (size_t)b * N_ * 32;
    float s[K_];
#pragma unroll
    for (int k = 0; k < K_; k++) {
        int j = __shfl_sync(0xffffffffu, jlane, k);
        float4 xv = Xv[(size_t)j * 32 + lane];
        float p = fmaf(q.x, xv.x, fmaf(q.y, xv.y, fmaf(q.z, xv.z, q.w * xv.w)));
#pragma unroll
        for (int off = 16; off > 0; off >>= 1)
            p += __shfl_xor_sync(0xffffffffu, p, off);
        s[k] = p;                               // all lanes hold the full dot
    }

    const float scale = 0.08838834764831845f;   // 1/sqrt(128)
    float m = s[0] * scale;
#pragma unroll
    for (int k = 1; k < K_; k++) m = fmaxf(m, s[k] * scale);
    float sum = 0.f;
#pragma unroll
    for (int k = 0; k < K_; k++) {
        s[k] = __expf(fmaf(s[k], scale, -m));
        sum += s[k];
    }
    const float inv = 1.f / sum;

    float4 a0 = make_float4(0.f, 0.f, 0.f, 0.f);
    float4 a1 = make_float4(0.f, 0.f, 0.f, 0.f);
    const float4* Fv = (const float4*)g_Ft + (size_t)b * N_ * 64;
#pragma unroll
    for (int k = 0; k < K_; k++) {
        int j = __shfl_sync(0xffffffffu, jlane, k);
        float ak = s[k] * inv;
        float4 f0 = Fv[(size_t)j * 64 + lane];
        float4 f1 = Fv[(size_t)j * 64 + 32 + lane];
        a0.x = fmaf(ak, f0.x, a0.x); a0.y = fmaf(ak, f0.y, a0.y);
        a0.z = fmaf(ak, f0.z, a0.z); a0.w = fmaf(ak, f0.w, a0.w);
        a1.x = fmaf(ak, f1.x, a1.x); a1.y = fmaf(ak, f1.y, a1.y);
        a1.z = fmaf(ak, f1.z, a1.z); a1.w = fmaf(ak, f1.w, a1.w);
    }

    // stage: channels 4*lane..4*lane+3 (a0) and 128+4*lane.. (a1), column w
    int cb = 4 * lane;
    tile[(cb + 0) * 33 + w] = a0.x;
    tile[(cb + 1) * 33 + w] = a0.y;
    tile[(cb + 2) * 33 + w] = a0.z;
    tile[(cb + 3) * 33 + w] = a0.w;
    tile[(C_ / 2 + cb + 0) * 33 + w] = a1.x;
    tile[(C_ / 2 + cb + 1) * 33 + w] = a1.y;
    tile[(C_ / 2 + cb + 2) * 33 + w] = a1.z;
    tile[(C_ / 2 + cb + 3) * 33 + w] = a1.w;
    __syncthreads();

    // coalesced write: lanes sweep n, rows sweep c
    float* ob = out + (size_t)b * C_ * N_;
#pragma unroll
    for (int r = 0; r < 8; r++) {
        int c = w + r * 32;
        ob[(size_t)c * N_ + n0 + lane] = tile[c * 33 + lane];
    }
}

// ---------------- launch ------------------------------------------------------
extern "C" void kernel_launch(void* const* d_in, const int* in_sizes, int n_in,
                              void* d_out, int out_size) {
    (void)in_sizes; (void)n_in; (void)out_size;
    const float* xyz = (const float*)d_in[0];   // [B,N,3]
    const float* F   = (const float*)d_in[1];   // [B,C,N]
    const float* X   = (const float*)d_in[2];   // [B,N,D]
    const float* Wq  = (const float*)d_in[3];
    const float* bq  = (const float*)d_in[4];
    const float* Wk  = (const float*)d_in[5];
    float* out = (float*)d_out;                 // [B,C,N]

    cudaFuncSetAttribute(knn_kernel, cudaFuncAttributeMaxDynamicSharedMemorySize, 65536);
    cudaFuncSetAttribute(qt_kernel,  cudaFuncAttributeMaxDynamicSharedMemorySize, 65536);

    fold_kernel<<<D_, D_>>>(Wq, Wk, bq);
    knn_kernel<<<dim3(N_ / 128, B_), 128, 65536>>>(xyz);
    qt_kernel<<<(B_ * N_) / 32, 1024, 65536>>>(X);
    transpose_kernel<<<dim3(N_ / 32, C_ / 32, B_), dim3(32, 8)>>>(F);
    attn_kernel<<<dim3(N_ / 32, B_), 1024>>>(X, out);
}

// round 2
// speedup vs baseline: 1.5273x; 1.5273x over previous
#include <cuda_runtime.h>
#include <cuda_fp16.h>
#include <math_constants.h>
#include <cstdint>

// Problem constants (fixed shapes)
#define B_  8
#define N_  4096
#define D_  128
#define C_  256
#define K_  16

// ---------------- scratch (device globals; allocation-free rule) -------------
__device__ float  g_M[D_ * D_];                  // WqT * Wk
__device__ float  g_v[D_];                       // bq * Wk
__device__ int    g_idx[B_ * N_ * K_];           // knn indices
__device__ float  g_qt[(size_t)B_ * N_ * D_];    // folded query (fp32)
__device__ __half g_Ft[(size_t)B_ * N_ * C_];    // transposed features [B,N,C] fp16
__device__ __half g_X16[(size_t)B_ * N_ * D_];   // concat features [B,N,D] fp16

// ---------------- K0: fold weights ------------------------------------------
// M[c,d] = sum_e Wq[e,c] * Wk[e,d];  v[d] = sum_e bq[e] * Wk[e,d]
__global__ void fold_kernel(const float* __restrict__ Wq,
                            const float* __restrict__ Wk,
                            const float* __restrict__ bq) {
    int c = blockIdx.x;      // 0..127
    int d = threadIdx.x;     // 0..127
    float acc = 0.f;
#pragma unroll 8
    for (int e = 0; e < D_; e++)
        acc = fmaf(Wq[e * D_ + c], Wk[e * D_ + d], acc);
    g_M[c * D_ + d] = acc;
    if (c == 0) {
        float a2 = 0.f;
#pragma unroll 8
        for (int e = 0; e < D_; e++)
            a2 = fmaf(bq[e], Wk[e * D_ + d], a2);
        g_v[d] = a2;
    }
}

// ---------------- K1: KNN, two-pass (values bubble, then index recovery) -----
// Thread per query. d2 = (|q|^2 + |c|^2) - 2*inner  (>= 0; exact 0 for self).
// Pass 1 keeps the 16 smallest VALUES in a sorted register list; insert is a
// predicate-free 15-stage FMNMX bubble (30 ops). Pass 2 re-scans and emits the
// indices of all d2 <= vb[15] (<=16, tie-capped, ascending j like jax top_k).
__global__ __launch_bounds__(128) void knn_kernel(const float* __restrict__ xyz) {
    extern __shared__ float4 spts[];            // [N_] (x,y,z,|x|^2) = 64KB
    const int b = blockIdx.y;
    const float* base = xyz + (size_t)b * N_ * 3;

    for (int j = threadIdx.x; j < N_; j += 128) {
        float x = base[j * 3 + 0];
        float y = base[j * 3 + 1];
        float z = base[j * 3 + 2];
        spts[j] = make_float4(x, y, z, fmaf(x, x, fmaf(y, y, z * z)));
    }
    __syncthreads();

    const int n = blockIdx.x * 128 + threadIdx.x;
    const float4 q = spts[n];

    float vb[K_];
#pragma unroll
    for (int t = 0; t < K_; t++) vb[t] = CUDART_INF_F;

#pragma unroll 4
    for (int j = 0; j < N_; j++) {
        float4 c = spts[j];
        float inner = fmaf(q.x, c.x, fmaf(q.y, c.y, q.z * c.z));
        float d2 = fmaf(-2.f, inner, q.w + c.w);
        if (d2 < vb[K_ - 1]) {
            vb[K_ - 1] = d2;
#pragma unroll
            for (int t = K_ - 1; t > 0; t--) {
                float lo = fminf(vb[t - 1], vb[t]);
                float hi = fmaxf(vb[t - 1], vb[t]);
                vb[t - 1] = lo; vb[t] = hi;
            }
        }
    }

    const float thr = vb[K_ - 1];
    int cnt = 0;
    int* out = g_idx + ((size_t)b * N_ + n) * K_;
#pragma unroll 4
    for (int j = 0; j < N_; j++) {
        float4 c = spts[j];
        float inner = fmaf(q.x, c.x, fmaf(q.y, c.y, q.z * c.z));
        float d2 = fmaf(-2.f, inner, q.w + c.w);
        if (d2 <= thr && cnt < K_) out[cnt++] = j;
    }
}

// ---------------- K2: qt = X @ M + v, 4 rows per warp ------------------------
// M staged in 64KB smem; each M float4 load is reused by 4 output rows, so
// smem traffic drops 4x vs 1 row/warp -> FFMA-pipe bound.
__global__ __launch_bounds__(1024) void qt_kernel(const float* __restrict__ X) {
    extern __shared__ float Ms[];               // 128*128 floats = 64KB
    for (int i = threadIdx.x; i < D_ * D_; i += 1024) Ms[i] = g_M[i];
    __syncthreads();

    const int warp = threadIdx.x >> 5, lane = threadIdx.x & 31;
    const int r0 = (blockIdx.x * 32 + warp) * 4;   // 256 blocks * 32 warps * 4 rows

    float xr[4][4];
#pragma unroll
    for (int r = 0; r < 4; r++)
#pragma unroll
        for (int t = 0; t < 4; t++)
            xr[r][t] = X[(size_t)(r0 + r) * D_ + lane + 32 * t];

    const float4* Ms4 = (const float4*)Ms;
    const float4 vinit = ((const float4*)g_v)[lane];
    float4 acc[4] = {vinit, vinit, vinit, vinit};

#pragma unroll
    for (int t = 0; t < 4; t++) {
#pragma unroll 4
        for (int l = 0; l < 32; l++) {
            float4 m = Ms4[(t * 32 + l) * 32 + lane];
#pragma unroll
            for (int r = 0; r < 4; r++) {
                float xc = __shfl_sync(0xffffffffu, xr[r][t], l);
                acc[r].x = fmaf(xc, m.x, acc[r].x);
                acc[r].y = fmaf(xc, m.y, acc[r].y);
                acc[r].z = fmaf(xc, m.z, acc[r].z);
                acc[r].w = fmaf(xc, m.w, acc[r].w);
            }
        }
    }
#pragma unroll
    for (int r = 0; r < 4; r++)
        ((float4*)g_qt)[(size_t)(r0 + r) * 32 + lane] = acc[r];
}

// ---------------- K3: transpose fp4_features [B,C,N] -> [B,N,C] fp16 ---------
__global__ void transpose_kernel(const float* __restrict__ F) {
    __shared__ float t[32][33];
    const int b = blockIdx.z;
    const int n0 = blockIdx.x * 32, c0 = blockIdx.y * 32;
    const int tx = threadIdx.x, ty = threadIdx.y;
    const float* Fb = F + (size_t)b * C_ * N_;
#pragma unroll
    for (int i = 0; i < 4; i++)
        t[ty + 8 * i][tx] = Fb[(size_t)(c0 + ty + 8 * i) * N_ + n0 + tx];
    __syncthreads();
    __half* Ftb = g_Ft + (size_t)b * N_ * C_;
#pragma unroll
    for (int i = 0; i < 4; i++)
        Ftb[(size_t)(n0 + ty + 8 * i) * C_ + c0 + tx] = __float2half(t[tx][ty + 8 * i]);
}

// ---------------- K3b: X (concat features) fp32 -> fp16 ----------------------
__global__ void xhalf_kernel(const float* __restrict__ X) {
    size_t i = (size_t)blockIdx.x * blockDim.x + threadIdx.x;  // one float4 each
    float4 v = ((const float4*)X)[i];
    __half2 a = __floats2half2_rn(v.x, v.y);
    __half2 b = __floats2half2_rn(v.z, v.w);
    uint2 u;
    u.x = *(const unsigned int*)&a;
    u.y = *(const unsigned int*)&b;
    ((uint2*)g_X16)[i] = u;
}

// ---------------- K4: scores + softmax + weighted gather + coalesced out -----
// Warp per point (32 points/block). Gathers use fp16 tables (half traffic).
__global__ __launch_bounds__(1024) void attn_kernel(float* __restrict__ out) {
    __shared__ float tile[32 * 258];            // [point][channel], pad 258

    const int w = threadIdx.x >> 5, lane = threadIdx.x & 31;
    const int b = blockIdx.y;
    const int n0 = blockIdx.x * 32;
    const int n = n0 + w;
    const size_t pt = (size_t)b * N_ + n;

    const float4 q = ((const float4*)g_qt)[pt * 32 + lane];    // ch 4L..4L+3
    int jlane = (lane < K_) ? g_idx[pt * K_ + lane] : 0;

    // scores: s_k = qt . X16[j_k]  (row = 128 half = 32 uint2)
    const uint2* Xv = (const uint2*)g_X16 + (size_t)b * N_ * 32;
    float s[K_];
#pragma unroll
    for (int k = 0; k < K_; k++) {
        int j = __shfl_sync(0xffffffffu, jlane, k);
        uint2 xv = Xv[(size_t)j * 32 + lane];
        float2 f0 = __half22float2(*(const __half2*)&xv.x);
        float2 f1 = __half22float2(*(const __half2*)&xv.y);
        float p = fmaf(q.x, f0.x, fmaf(q.y, f0.y, fmaf(q.z, f1.x, q.w * f1.y)));
#pragma unroll
        for (int off = 16; off > 0; off >>= 1)
            p += __shfl_xor_sync(0xffffffffu, p, off);
        s[k] = p;
    }

    const float scale = 0.08838834764831845f;   // 1/sqrt(128)
    float m = s[0] * scale;
#pragma unroll
    for (int k = 1; k < K_; k++) m = fmaxf(m, s[k] * scale);
    float sum = 0.f;
#pragma unroll
    for (int k = 0; k < K_; k++) {
        s[k] = __expf(fmaf(s[k], scale, -m));
        sum += s[k];
    }
    const float inv = 1.f / sum;

    // weighted feature gather: Ft16 row = 256 half = 32 uint4; lane ch 8L..8L+7
    float a[8] = {0.f, 0.f, 0.f, 0.f, 0.f, 0.f, 0.f, 0.f};
    const uint4* Fv = (const uint4*)g_Ft + (size_t)b * N_ * 32;
#pragma unroll
    for (int k = 0; k < K_; k++) {
        int j = __shfl_sync(0xffffffffu, jlane, k);
        float ak = s[k] * inv;
        uint4 f = Fv[(size_t)j * 32 + lane];
        float2 p0 = __half22float2(*(const __half2*)&f.x);
        float2 p1 = __half22float2(*(const __half2*)&f.y);
        float2 p2 = __half22float2(*(const __half2*)&f.z);
        float2 p3 = __half22float2(*(const __half2*)&f.w);
        a[0] = fmaf(ak, p0.x, a[0]); a[1] = fmaf(ak, p0.y, a[1]);
        a[2] = fmaf(ak, p1.x, a[2]); a[3] = fmaf(ak, p1.y, a[3]);
        a[4] = fmaf(ak, p2.x, a[4]); a[5] = fmaf(ak, p2.y, a[5]);
        a[6] = fmaf(ak, p3.x, a[6]); a[7] = fmaf(ak, p3.y, a[7]);
    }

    // stage [point][channel]; float2 stores, reads are 2-way-conflict max
    float* trow = &tile[w * 258 + 8 * lane];
#pragma unroll
    for (int i = 0; i < 4; i++)
        ((float2*)trow)[i] = make_float2(a[2 * i], a[2 * i + 1]);
    __syncthreads();

    // coalesced write: lanes sweep n, rows sweep c
    float* ob = out + (size_t)b * C_ * N_;
#pragma unroll
    for (int r = 0; r < 8; r++) {
        int c = w + r * 32;
        ob[(size_t)c * N_ + n0 + lane] = tile[lane * 258 + c];
    }
}

// ---------------- launch ------------------------------------------------------
extern "C" void kernel_launch(void* const* d_in, const int* in_sizes, int n_in,
                              void* d_out, int out_size) {
    (void)in_sizes; (void)n_in; (void)out_size;
    const float* xyz = (const float*)d_in[0];   // [B,N,3]
    const float* F   = (const float*)d_in[1];   // [B,C,N]
    const float* X   = (const float*)d_in[2];   // [B,N,D]
    const float* Wq  = (const float*)d_in[3];
    const float* bq  = (const float*)d_in[4];
    const float* Wk  = (const float*)d_in[5];
    float* out = (float*)d_out;                 // [B,C,N]

    cudaFuncSetAttribute(knn_kernel, cudaFuncAttributeMaxDynamicSharedMemorySize, 65536);
    cudaFuncSetAttribute(qt_kernel,  cudaFuncAttributeMaxDynamicSharedMemorySize, 65536);

    fold_kernel<<<D_, D_>>>(Wq, Wk, bq);
    transpose_kernel<<<dim3(N_ / 32, C_ / 32, B_), dim3(32, 8)>>>(F);
    xhalf_kernel<<<(B_ * N_ * D_ / 4) / 256, 256>>>(X);
    knn_kernel<<<dim3(N_ / 128, B_), 128, 65536>>>(xyz);
    qt_kernel<<<(B_ * N_) / 128, 1024, 65536>>>(X);
    attn_kernel<<<dim3(N_ / 32, B_), 1024>>>(out);
}

// round 3
// speedup vs baseline: 1.9745x; 1.2928x over previous
#include <cuda_runtime.h>
#include <cuda_fp16.h>
#include <math_constants.h>
#include <cstdint>

// Problem constants (fixed shapes)
#define B_  8
#define N_  4096
#define D_  128
#define C_  256
#define K_  16

// ---------------- scratch (device globals; allocation-free rule) -------------
__device__ float  g_M[D_ * D_];                  // WqT * Wk
__device__ float  g_v[D_];                       // bq * Wk
__device__ int    g_idx[B_ * N_ * K_];           // knn indices
__device__ float  g_qt[(size_t)B_ * N_ * D_];    // folded query (fp32)
__device__ __half g_Ft[(size_t)B_ * N_ * C_];    // transposed features [B,N,C] fp16
__device__ __half g_X16[(size_t)B_ * N_ * D_];   // concat features [B,N,D] fp16

// ---------------- K0: fold weights ------------------------------------------
__global__ void fold_kernel(const float* __restrict__ Wq,
                            const float* __restrict__ Wk,
                            const float* __restrict__ bq) {
    int c = blockIdx.x;      // 0..127
    int d = threadIdx.x;     // 0..127
    float acc = 0.f;
#pragma unroll 8
    for (int e = 0; e < D_; e++)
        acc = fmaf(Wq[e * D_ + c], Wk[e * D_ + d], acc);
    g_M[c * D_ + d] = acc;
    if (c == 0) {
        float a2 = 0.f;
#pragma unroll 8
        for (int e = 0; e < D_; e++)
            a2 = fmaf(bq[e], Wk[e * D_ + d], a2);
        g_v[d] = a2;
    }
}

// ---------------- K1: KNN, 4 threads per query -------------------------------
// Each query's 4096-point scan is split over 4 adjacent lanes (strided pairs:
// thread c handles j = 8k + 2c + {0,1}). Each lane keeps the 16 smallest d2
// VALUES in a sorted register list (FMNMX bubble insert). The 4 lists are
// merged exactly with a 2-stage shfl bitonic min-merge; the 16th value is the
// threshold. A second scan recovers indices (<=16, tie-capped), compacted via
// shfl prefix sums. Neighbor order differs from reference but downstream
// (softmax + weighted sum) is permutation-invariant.
__global__ __launch_bounds__(512, 2) void knn_kernel(const float* __restrict__ xyz) {
    extern __shared__ float4 spts[];            // [N_] (x,y,z,|x|^2) = 64KB
    __shared__ int cand[512 * K_];              // 32KB candidate buffer
    const int b = blockIdx.y;
    const float* base = xyz + (size_t)b * N_ * 3;
    const int tid = threadIdx.x;

    for (int j = tid; j < N_; j += 512) {
        float x = base[j * 3 + 0];
        float y = base[j * 3 + 1];
        float z = base[j * 3 + 2];
        spts[j] = make_float4(x, y, z, fmaf(x, x, fmaf(y, y, z * z)));
    }
    __syncthreads();

    const int qloc = tid >> 2, c = tid & 3;
    const int n = blockIdx.x * 128 + qloc;
    const float4 q = spts[n];

    float vb[K_];
#pragma unroll
    for (int t = 0; t < K_; t++) vb[t] = CUDART_INF_F;

    // ---- pass 1: values-only top-16 over strided pairs ----
    for (int k = 0; k < N_ / 8; k++) {
        const int j0 = 8 * k + 2 * c;
        float4 p0 = spts[j0];
        float4 p1 = spts[j0 + 1];
        float d0 = fmaf(-2.f, fmaf(q.x, p0.x, fmaf(q.y, p0.y, q.z * p0.z)), q.w + p0.w);
        float d1 = fmaf(-2.f, fmaf(q.x, p1.x, fmaf(q.y, p1.y, q.z * p1.z)), q.w + p1.w);
        float mn = fminf(d0, d1), mx = fmaxf(d0, d1);
        if (mn < vb[K_ - 1]) {
            vb[K_ - 1] = mn;
#pragma unroll
            for (int t = K_ - 1; t > 0; t--) {
                float lo = fminf(vb[t - 1], vb[t]);
                float hi = fmaxf(vb[t - 1], vb[t]);
                vb[t - 1] = lo; vb[t] = hi;
            }
            if (mx < vb[K_ - 1]) {
                vb[K_ - 1] = mx;
#pragma unroll
                for (int t = K_ - 1; t > 0; t--) {
                    float lo = fminf(vb[t - 1], vb[t]);
                    float hi = fmaxf(vb[t - 1], vb[t]);
                    vb[t - 1] = lo; vb[t] = hi;
                }
            }
        }
    }

    // ---- exact merge of the 4 sorted lists (lanes 4q..4q+3) ----
#pragma unroll
    for (int stage = 1; stage <= 2; stage <<= 1) {
        float nb[K_];
#pragma unroll
        for (int t = 0; t < K_; t++) {
            float o = __shfl_xor_sync(0xffffffffu, vb[K_ - 1 - t], stage);
            nb[t] = fminf(vb[t], o);            // 16 smallest of union (bitonic)
        }
#pragma unroll
        for (int kk = 8; kk >= 1; kk >>= 1) {   // sort bitonic sequence
#pragma unroll
            for (int t = 0; t < K_; t++) {
                if ((t & kk) == 0) {
                    float lo = fminf(nb[t], nb[t | kk]);
                    float hi = fmaxf(nb[t], nb[t | kk]);
                    nb[t] = lo; nb[t | kk] = hi;
                }
            }
        }
#pragma unroll
        for (int t = 0; t < K_; t++) vb[t] = nb[t];
    }
    const float thr = vb[K_ - 1];

    // ---- pass 2: index recovery into smem (identical arithmetic) ----
    int cnt = 0;
    int* my = cand + tid * K_;
    for (int k = 0; k < N_ / 8; k++) {
        const int j0 = 8 * k + 2 * c;
        float4 p0 = spts[j0];
        float4 p1 = spts[j0 + 1];
        float d0 = fmaf(-2.f, fmaf(q.x, p0.x, fmaf(q.y, p0.y, q.z * p0.z)), q.w + p0.w);
        float d1 = fmaf(-2.f, fmaf(q.x, p1.x, fmaf(q.y, p1.y, q.z * p1.z)), q.w + p1.w);
        if (d0 <= thr) { if (cnt < K_) my[cnt] = j0;     cnt++; }
        if (d1 <= thr) { if (cnt < K_) my[cnt] = j0 + 1; cnt++; }
    }
    if (cnt > K_) cnt = K_;

    // ---- prefix offsets across the 4 chunk lanes, capped write ----
    const int lane = tid & 31, gbase = lane & ~3;
    int off = 0;
#pragma unroll
    for (int cc = 0; cc < 3; cc++) {
        int ocnt = __shfl_sync(0xffffffffu, cnt, gbase + cc);
        if (cc < c) off += ocnt;
    }
    int* out = g_idx + ((size_t)b * N_ + n) * K_;
    for (int i = 0; i < cnt && off + i < K_; i++)
        out[off + i] = my[i];
}

// ---------------- K2: qt = X @ M + v, 4 rows per warp ------------------------
__global__ __launch_bounds__(1024) void qt_kernel(const float* __restrict__ X) {
    extern __shared__ float Ms[];               // 128*128 floats = 64KB
    for (int i = threadIdx.x; i < D_ * D_; i += 1024) Ms[i] = g_M[i];
    __syncthreads();

    const int warp = threadIdx.x >> 5, lane = threadIdx.x & 31;
    const int r0 = (blockIdx.x * 32 + warp) * 4;

    float xr[4][4];
#pragma unroll
    for (int r = 0; r < 4; r++)
#pragma unroll
        for (int t = 0; t < 4; t++)
            xr[r][t] = X[(size_t)(r0 + r) * D_ + lane + 32 * t];

    const float4* Ms4 = (const float4*)Ms;
    const float4 vinit = ((const float4*)g_v)[lane];
    float4 acc[4] = {vinit, vinit, vinit, vinit};

#pragma unroll
    for (int t = 0; t < 4; t++) {
#pragma unroll 4
        for (int l = 0; l < 32; l++) {
            float4 m = Ms4[(t * 32 + l) * 32 + lane];
#pragma unroll
            for (int r = 0; r < 4; r++) {
                float xc = __shfl_sync(0xffffffffu, xr[r][t], l);
                acc[r].x = fmaf(xc, m.x, acc[r].x);
                acc[r].y = fmaf(xc, m.y, acc[r].y);
                acc[r].z = fmaf(xc, m.z, acc[r].z);
                acc[r].w = fmaf(xc, m.w, acc[r].w);
            }
        }
    }
#pragma unroll
    for (int r = 0; r < 4; r++)
        ((float4*)g_qt)[(size_t)(r0 + r) * 32 + lane] = acc[r];
}

// ---------------- K3: transpose fp4_features [B,C,N] -> [B,N,C] fp16 ---------
__global__ void transpose_kernel(const float* __restrict__ F) {
    __shared__ float t[32][33];
    const int b = blockIdx.z;
    const int n0 = blockIdx.x * 32, c0 = blockIdx.y * 32;
    const int tx = threadIdx.x, ty = threadIdx.y;
    const float* Fb = F + (size_t)b * C_ * N_;
#pragma unroll
    for (int i = 0; i < 4; i++)
        t[ty + 8 * i][tx] = Fb[(size_t)(c0 + ty + 8 * i) * N_ + n0 + tx];
    __syncthreads();
    __half* Ftb = g_Ft + (size_t)b * N_ * C_;
#pragma unroll
    for (int i = 0; i < 4; i++)
        Ftb[(size_t)(n0 + ty + 8 * i) * C_ + c0 + tx] = __float2half(t[tx][ty + 8 * i]);
}

// ---------------- K3b: X (concat features) fp32 -> fp16 ----------------------
__global__ void xhalf_kernel(const float* __restrict__ X) {
    size_t i = (size_t)blockIdx.x * blockDim.x + threadIdx.x;  // one float4 each
    float4 v = ((const float4*)X)[i];
    __half2 a = __floats2half2_rn(v.x, v.y);
    __half2 b = __floats2half2_rn(v.z, v.w);
    uint2 u;
    u.x = *(const unsigned int*)&a;
    u.y = *(const unsigned int*)&b;
    ((uint2*)g_X16)[i] = u;
}

// ---------------- K4: scores + softmax + weighted gather + coalesced out -----
__global__ __launch_bounds__(1024) void attn_kernel(float* __restrict__ out) {
    __shared__ float tile[32 * 258];            // [point][channel], pad 258

    const int w = threadIdx.x >> 5, lane = threadIdx.x & 31;
    const int b = blockIdx.y;
    const int n0 = blockIdx.x * 32;
    const int n = n0 + w;
    const size_t pt = (size_t)b * N_ + n;

    const float4 q = ((const float4*)g_qt)[pt * 32 + lane];    // ch 4L..4L+3
    int jlane = (lane < K_) ? g_idx[pt * K_ + lane] : 0;

    // scores: s_k = qt . X16[j_k]  (row = 128 half = 32 uint2)
    const uint2* Xv = (const uint2*)g_X16 + (size_t)b * N_ * 32;
    float s[K_];
#pragma unroll
    for (int k = 0; k < K_; k++) {
        int j = __shfl_sync(0xffffffffu, jlane, k);
        uint2 xv = Xv[(size_t)j * 32 + lane];
        float2 f0 = __half22float2(*(const __half2*)&xv.x);
        float2 f1 = __half22float2(*(const __half2*)&xv.y);
        float p = fmaf(q.x, f0.x, fmaf(q.y, f0.y, fmaf(q.z, f1.x, q.w * f1.y)));
#pragma unroll
        for (int off = 16; off > 0; off >>= 1)
            p += __shfl_xor_sync(0xffffffffu, p, off);
        s[k] = p;
    }

    const float scale = 0.08838834764831845f;   // 1/sqrt(128)
    float m = s[0] * scale;
#pragma unroll
    for (int k = 1; k < K_; k++) m = fmaxf(m, s[k] * scale);
    float sum = 0.f;
#pragma unroll
    for (int k = 0; k < K_; k++) {
        s[k] = __expf(fmaf(s[k], scale, -m));
        sum += s[k];
    }
    const float inv = 1.f / sum;

    // weighted feature gather: Ft16 row = 256 half = 32 uint4; lane ch 8L..8L+7
    float a[8] = {0.f, 0.f, 0.f, 0.f, 0.f, 0.f, 0.f, 0.f};
    const uint4* Fv = (const uint4*)g_Ft + (size_t)b * N_ * 32;
#pragma unroll
    for (int k = 0; k < K_; k++) {
        int j = __shfl_sync(0xffffffffu, jlane, k);
        float ak = s[k] * inv;
        uint4 f = Fv[(size_t)j * 32 + lane];
        float2 p0 = __half22float2(*(const __half2*)&f.x);
        float2 p1 = __half22float2(*(const __half2*)&f.y);
        float2 p2 = __half22float2(*(const __half2*)&f.z);
        float2 p3 = __half22float2(*(const __half2*)&f.w);
        a[0] = fmaf(ak, p0.x, a[0]); a[1] = fmaf(ak, p0.y, a[1]);
        a[2] = fmaf(ak, p1.x, a[2]); a[3] = fmaf(ak, p1.y, a[3]);
        a[4] = fmaf(ak, p2.x, a[4]); a[5] = fmaf(ak, p2.y, a[5]);
        a[6] = fmaf(ak, p3.x, a[6]); a[7] = fmaf(ak, p3.y, a[7]);
    }

    // stage [point][channel]; float2 stores, reads are 2-way-conflict max
    float* trow = &tile[w * 258 + 8 * lane];
#pragma unroll
    for (int i = 0; i < 4; i++)
        ((float2*)trow)[i] = make_float2(a[2 * i], a[2 * i + 1]);
    __syncthreads();

    // coalesced write: lanes sweep n, rows sweep c
    float* ob = out + (size_t)b * C_ * N_;
#pragma unroll
    for (int r = 0; r < 8; r++) {
        int c = w + r * 32;
        ob[(size_t)c * N_ + n0 + lane] = tile[lane * 258 + c];
    }
}

// ---------------- launch ------------------------------------------------------
extern "C" void kernel_launch(void* const* d_in, const int* in_sizes, int n_in,
                              void* d_out, int out_size) {
    (void)in_sizes; (void)n_in; (void)out_size;
    const float* xyz = (const float*)d_in[0];   // [B,N,3]
    const float* F   = (const float*)d_in[1];   // [B,C,N]
    const float* X   = (const float*)d_in[2];   // [B,N,D]
    const float* Wq  = (const float*)d_in[3];
    const float* bq  = (const float*)d_in[4];
    const float* Wk  = (const float*)d_in[5];
    float* out = (float*)d_out;                 // [B,C,N]

    cudaFuncSetAttribute(knn_kernel, cudaFuncAttributeMaxDynamicSharedMemorySize, 65536);
    cudaFuncSetAttribute(qt_kernel,  cudaFuncAttributeMaxDynamicSharedMemorySize, 65536);

    fold_kernel<<<D_, D_>>>(Wq, Wk, bq);
    transpose_kernel<<<dim3(N_ / 32, C_ / 32, B_), dim3(32, 8)>>>(F);
    xhalf_kernel<<<(B_ * N_ * D_ / 4) / 256, 256>>>(X);
    knn_kernel<<<dim3(N_ / 128, B_), 512, 65536>>>(xyz);
    qt_kernel<<<(B_ * N_) / 128, 1024, 65536>>>(X);
    attn_kernel<<<dim3(N_ / 32, B_), 1024>>>(out);
}

// round 4
// speedup vs baseline: 2.4105x; 1.2208x over previous
#include <cuda_runtime.h>
#include <cuda_fp16.h>
#include <math_constants.h>
#include <cstdint>

// Problem constants (fixed shapes)
#define B_  8
#define N_  4096
#define D_  128
#define C_  256
#define K_  16

// ---------------- scratch (device globals; allocation-free rule) -------------
__device__ float  g_M[D_ * D_];                  // WqT * Wk
__device__ float  g_v[D_];                       // bq * Wk
__device__ int    g_idx[B_ * N_ * K_];           // knn indices
__device__ float  g_qt[(size_t)B_ * N_ * D_];    // folded query (fp32)
__device__ __half g_Ft[(size_t)B_ * N_ * C_];    // transposed features [B,N,C] fp16
__device__ __half g_X16[(size_t)B_ * N_ * D_];   // concat features [B,N,D] fp16

// ---------------- K0: fold weights ------------------------------------------
__global__ void fold_kernel(const float* __restrict__ Wq,
                            const float* __restrict__ Wk,
                            const float* __restrict__ bq) {
    int c = blockIdx.x;      // 0..127
    int d = threadIdx.x;     // 0..127
    float acc = 0.f;
#pragma unroll 8
    for (int e = 0; e < D_; e++)
        acc = fmaf(Wq[e * D_ + c], Wk[e * D_ + d], acc);
    g_M[c * D_ + d] = acc;
    if (c == 0) {
        float a2 = 0.f;
#pragma unroll 8
        for (int e = 0; e < D_; e++)
            a2 = fmaf(bq[e], Wk[e * D_ + d], a2);
        g_v[d] = a2;
    }
}

// ---------------- K1: KNN, one WARP per query, distributed top-16 ------------
// The sorted 16-smallest list lives across lanes 0..15 (one (value,index) pair
// per lane, ascending). Each iteration all 32 lanes evaluate 32 candidates and
// ballot against the shared threshold t = a[15]. Each qualifying candidate is
// inserted warp-cooperatively:
//   a'[l] = min(max(a[l-1], d), a[l])   (one shfl_up + FMNMX pair)
// with the index following via two selects. Events ~110/query total, so the
// insert path runs ~0.9x per iteration instead of the per-lane-list design's
// guaranteed-every-iteration bubble. Single pass, exact, no index-recovery
// rescan. Neighbor set identical up to fp rounding of d2; order by distance.
__global__ __launch_bounds__(1024) void knn_kernel(const float* __restrict__ xyz) {
    extern __shared__ float4 spts[];            // [N_] (x,y,z,|x|^2) = 64KB
    const int b = blockIdx.y;
    const int tid = threadIdx.x;

    // stage points: thread t loads 3 float4 (= 4 points), fully coalesced
    {
        const float4* xin = (const float4*)(xyz + (size_t)b * N_ * 3);
        float4 A = xin[3 * tid + 0];
        float4 Bv = xin[3 * tid + 1];
        float4 Cv = xin[3 * tid + 2];
        float x0 = A.x,  y0 = A.y,  z0 = A.z;
        float x1 = A.w,  y1 = Bv.x, z1 = Bv.y;
        float x2 = Bv.z, y2 = Bv.w, z2 = Cv.x;
        float x3 = Cv.y, y3 = Cv.z, z3 = Cv.w;
        spts[4 * tid + 0] = make_float4(x0, y0, z0, fmaf(x0, x0, fmaf(y0, y0, z0 * z0)));
        spts[4 * tid + 1] = make_float4(x1, y1, z1, fmaf(x1, x1, fmaf(y1, y1, z1 * z1)));
        spts[4 * tid + 2] = make_float4(x2, y2, z2, fmaf(x2, x2, fmaf(y2, y2, z2 * z2)));
        spts[4 * tid + 3] = make_float4(x3, y3, z3, fmaf(x3, x3, fmaf(y3, y3, z3 * z3)));
    }
    __syncthreads();

    const int lane = tid & 31, w = tid >> 5;
    const int n = blockIdx.x * 32 + w;          // query for this warp
    const float4 q = spts[n];

    float a  = CUDART_INF_F;                    // distributed sorted list (lanes 0..15)
    int   il = 0;
    float t  = CUDART_INF_F;                    // shared threshold = a[15]

    for (int i = 0; i < N_ / 32; i++) {
        const int j = i * 32 + lane;
        float4 p = spts[j];
        float inner = fmaf(q.x, p.x, fmaf(q.y, p.y, q.z * p.z));
        float d = fmaf(-2.f, inner, q.w + p.w);

        unsigned mask = __ballot_sync(0xffffffffu, d < t);
        while (mask) {
            const int src = __ffs(mask) - 1;
            mask &= mask - 1;
            const float dd = __shfl_sync(0xffffffffu, d, src);
            if (dd < t) {                        // uniform re-check (t tightened)
                const int jj = i * 32 + src;
                float au = __shfl_up_sync(0xffffffffu, a, 1);
                int   iu = __shfl_up_sync(0xffffffffu, il, 1);
                if (lane == 0) au = -CUDART_INF_F;
                const float an = fminf(fmaxf(au, dd), a);
                il = (dd >= a) ? il : ((au <= dd) ? jj : iu);
                a = an;
                t = __shfl_sync(0xffffffffu, a, 15);
            }
        }
    }

    if (lane < K_)
        g_idx[((size_t)b * N_ + n) * K_ + lane] = il;
}

// ---------------- K2: qt = X @ M + v, 4 rows per warp ------------------------
__global__ __launch_bounds__(1024) void qt_kernel(const float* __restrict__ X) {
    extern __shared__ float Ms[];               // 128*128 floats = 64KB
    for (int i = threadIdx.x; i < D_ * D_; i += 1024) Ms[i] = g_M[i];
    __syncthreads();

    const int warp = threadIdx.x >> 5, lane = threadIdx.x & 31;
    const int r0 = (blockIdx.x * 32 + warp) * 4;

    float xr[4][4];
#pragma unroll
    for (int r = 0; r < 4; r++)
#pragma unroll
        for (int t = 0; t < 4; t++)
            xr[r][t] = X[(size_t)(r0 + r) * D_ + lane + 32 * t];

    const float4* Ms4 = (const float4*)Ms;
    const float4 vinit = ((const float4*)g_v)[lane];
    float4 acc[4] = {vinit, vinit, vinit, vinit};

#pragma unroll
    for (int t = 0; t < 4; t++) {
#pragma unroll 4
        for (int l = 0; l < 32; l++) {
            float4 m = Ms4[(t * 32 + l) * 32 + lane];
#pragma unroll
            for (int r = 0; r < 4; r++) {
                float xc = __shfl_sync(0xffffffffu, xr[r][t], l);
                acc[r].x = fmaf(xc, m.x, acc[r].x);
                acc[r].y = fmaf(xc, m.y, acc[r].y);
                acc[r].z = fmaf(xc, m.z, acc[r].z);
                acc[r].w = fmaf(xc, m.w, acc[r].w);
            }
        }
    }
#pragma unroll
    for (int r = 0; r < 4; r++)
        ((float4*)g_qt)[(size_t)(r0 + r) * 32 + lane] = acc[r];
}

// ---------------- K3: transpose fp4_features [B,C,N] -> [B,N,C] fp16 ---------
__global__ void transpose_kernel(const float* __restrict__ F) {
    __shared__ float t[32][33];
    const int b = blockIdx.z;
    const int n0 = blockIdx.x * 32, c0 = blockIdx.y * 32;
    const int tx = threadIdx.x, ty = threadIdx.y;
    const float* Fb = F + (size_t)b * C_ * N_;
#pragma unroll
    for (int i = 0; i < 4; i++)
        t[ty + 8 * i][tx] = Fb[(size_t)(c0 + ty + 8 * i) * N_ + n0 + tx];
    __syncthreads();
    __half* Ftb = g_Ft + (size_t)b * N_ * C_;
#pragma unroll
    for (int i = 0; i < 4; i++)
        Ftb[(size_t)(n0 + ty + 8 * i) * C_ + c0 + tx] = __float2half(t[tx][ty + 8 * i]);
}

// ---------------- K3b: X (concat features) fp32 -> fp16 ----------------------
__global__ void xhalf_kernel(const float* __restrict__ X) {
    size_t i = (size_t)blockIdx.x * blockDim.x + threadIdx.x;  // one float4 each
    float4 v = ((const float4*)X)[i];
    __half2 a = __floats2half2_rn(v.x, v.y);
    __half2 b = __floats2half2_rn(v.z, v.w);
    uint2 u;
    u.x = *(const unsigned int*)&a;
    u.y = *(const unsigned int*)&b;
    ((uint2*)g_X16)[i] = u;
}

// ---------------- K4: scores + softmax + weighted gather + coalesced out -----
__global__ __launch_bounds__(1024) void attn_kernel(float* __restrict__ out) {
    __shared__ float tile[32 * 258];            // [point][channel], pad 258

    const int w = threadIdx.x >> 5, lane = threadIdx.x & 31;
    const int b = blockIdx.y;
    const int n0 = blockIdx.x * 32;
    const int n = n0 + w;
    const size_t pt = (size_t)b * N_ + n;

    const float4 q = ((const float4*)g_qt)[pt * 32 + lane];    // ch 4L..4L+3
    int jlane = (lane < K_) ? g_idx[pt * K_ + lane] : 0;

    // scores: s_k = qt . X16[j_k]  (row = 128 half = 32 uint2)
    const uint2* Xv = (const uint2*)g_X16 + (size_t)b * N_ * 32;
    float s[K_];
#pragma unroll
    for (int k = 0; k < K_; k++) {
        int j = __shfl_sync(0xffffffffu, jlane, k);
        uint2 xv = Xv[(size_t)j * 32 + lane];
        float2 f0 = __half22float2(*(const __half2*)&xv.x);
        float2 f1 = __half22float2(*(const __half2*)&xv.y);
        float p = fmaf(q.x, f0.x, fmaf(q.y, f0.y, fmaf(q.z, f1.x, q.w * f1.y)));
#pragma unroll
        for (int off = 16; off > 0; off >>= 1)
            p += __shfl_xor_sync(0xffffffffu, p, off);
        s[k] = p;
    }

    const float scale = 0.08838834764831845f;   // 1/sqrt(128)
    float m = s[0] * scale;
#pragma unroll
    for (int k = 1; k < K_; k++) m = fmaxf(m, s[k] * scale);
    float sum = 0.f;
#pragma unroll
    for (int k = 0; k < K_; k++) {
        s[k] = __expf(fmaf(s[k], scale, -m));
        sum += s[k];
    }
    const float inv = 1.f / sum;

    // weighted feature gather: Ft16 row = 256 half = 32 uint4; lane ch 8L..8L+7
    float a[8] = {0.f, 0.f, 0.f, 0.f, 0.f, 0.f, 0.f, 0.f};
    const uint4* Fv = (const uint4*)g_Ft + (size_t)b * N_ * 32;
#pragma unroll
    for (int k = 0; k < K_; k++) {
        int j = __shfl_sync(0xffffffffu, jlane, k);
        float ak = s[k] * inv;
        uint4 f = Fv[(size_t)j * 32 + lane];
        float2 p0 = __half22float2(*(const __half2*)&f.x);
        float2 p1 = __half22float2(*(const __half2*)&f.y);
        float2 p2 = __half22float2(*(const __half2*)&f.z);
        float2 p3 = __half22float2(*(const __half2*)&f.w);
        a[0] = fmaf(ak, p0.x, a[0]); a[1] = fmaf(ak, p0.y, a[1]);
        a[2] = fmaf(ak, p1.x, a[2]); a[3] = fmaf(ak, p1.y, a[3]);
        a[4] = fmaf(ak, p2.x, a[4]); a[5] = fmaf(ak, p2.y, a[5]);
        a[6] = fmaf(ak, p3.x, a[6]); a[7] = fmaf(ak, p3.y, a[7]);
    }

    // stage [point][channel]; float2 stores, reads are 2-way-conflict max
    float* trow = &tile[w * 258 + 8 * lane];
#pragma unroll
    for (int i = 0; i < 4; i++)
        ((float2*)trow)[i] = make_float2(a[2 * i], a[2 * i + 1]);
    __syncthreads();

    // coalesced write: lanes sweep n, rows sweep c
    float* ob = out + (size_t)b * C_ * N_;
#pragma unroll
    for (int r = 0; r < 8; r++) {
        int c = w + r * 32;
        ob[(size_t)c * N_ + n0 + lane] = tile[lane * 258 + c];
    }
}

// ---------------- launch ------------------------------------------------------
extern "C" void kernel_launch(void* const* d_in, const int* in_sizes, int n_in,
                              void* d_out, int out_size) {
    (void)in_sizes; (void)n_in; (void)out_size;
    const float* xyz = (const float*)d_in[0];   // [B,N,3]
    const float* F   = (const float*)d_in[1];   // [B,C,N]
    const float* X   = (const float*)d_in[2];   // [B,N,D]
    const float* Wq  = (const float*)d_in[3];
    const float* bq  = (const float*)d_in[4];
    const float* Wk  = (const float*)d_in[5];
    float* out = (float*)d_out;                 // [B,C,N]

    cudaFuncSetAttribute(knn_kernel, cudaFuncAttributeMaxDynamicSharedMemorySize, 65536);
    cudaFuncSetAttribute(qt_kernel,  cudaFuncAttributeMaxDynamicSharedMemorySize, 65536);

    fold_kernel<<<D_, D_>>>(Wq, Wk, bq);
    transpose_kernel<<<dim3(N_ / 32, C_ / 32, B_), dim3(32, 8)>>>(F);
    xhalf_kernel<<<(B_ * N_ * D_ / 4) / 256, 256>>>(X);
    knn_kernel<<<dim3(N_ / 32, B_), 1024, 65536>>>(xyz);
    qt_kernel<<<(B_ * N_) / 128, 1024, 65536>>>(X);
    attn_kernel<<<dim3(N_ / 32, B_), 1024>>>(out);
}

// round 6
// speedup vs baseline: 2.9141x; 1.2089x over previous
#include <cuda_runtime.h>
#include <cuda_fp16.h>
#include <math_constants.h>
#include <cstdint>

// Problem constants (fixed shapes)
#define B_  8
#define N_  4096
#define D_  128
#define C_  256
#define K_  16

// ---------------- scratch (device globals; allocation-free rule) -------------
__device__ float  g_M[D_ * D_];                  // WqT * Wk
__device__ float  g_v[D_];                       // bq * Wk
__device__ int    g_idx[B_ * N_ * K_];           // knn indices
__device__ float  g_qt[(size_t)B_ * N_ * D_];    // folded query (fp32)
__device__ __half g_Ft[(size_t)B_ * N_ * C_];    // transposed features [B,N,C] fp16
__device__ __half g_X16[(size_t)B_ * N_ * D_];   // concat features [B,N,D] fp16

// ---------------- K0: fold weights ------------------------------------------
__global__ void fold_kernel(const float* __restrict__ Wq,
                            const float* __restrict__ Wk,
                            const float* __restrict__ bq) {
    int c = blockIdx.x;      // 0..127
    int d = threadIdx.x;     // 0..127
    float acc = 0.f;
#pragma unroll 8
    for (int e = 0; e < D_; e++)
        acc = fmaf(Wq[e * D_ + c], Wk[e * D_ + d], acc);
    g_M[c * D_ + d] = acc;
    if (c == 0) {
        float a2 = 0.f;
#pragma unroll 8
        for (int e = 0; e < D_; e++)
            a2 = fmaf(bq[e], Wk[e * D_ + d], a2);
        g_v[d] = a2;
    }
}

// ---------------- K1: KNN, warp per query, distributed top-16 ----------------
// Selection key is EXACTLY round-4's d2 = fmaf(-2, q.p, |q|^2 + |p|^2)
// (measured rel_err 2.18e-4 downstream). List of 32 (d2, idx) pairs lives
// sorted-ASCENDING across the warp's lanes; threshold t = a[15] (16th
// smallest). Iteration 0 initializes the list with a warp bitonic KV sort.
// Scan iterations ballot d < t; qualifying candidates are inserted
// warp-cooperatively with a STALE t, refreshed once per firing iteration.
// Exactness of stale insert: the list holds 32 entries but only lanes 0..15
// are emitted, so a late insert of a non-top-16 candidate lands in lanes
// 16..31 and is harmless.
__global__ __launch_bounds__(1024) void knn_kernel(const float* __restrict__ xyz) {
    extern __shared__ float4 spts[];            // [N_] (x,y,z,|p|^2) = 64KB
    const int b = blockIdx.y;
    const int tid = threadIdx.x;

    // stage points: thread t loads 3 float4 (= 4 points), fully coalesced
    {
        const float4* xin = (const float4*)(xyz + (size_t)b * N_ * 3);
        float4 A = xin[3 * tid + 0];
        float4 Bv = xin[3 * tid + 1];
        float4 Cv = xin[3 * tid + 2];
        float x0 = A.x,  y0 = A.y,  z0 = A.z;
        float x1 = A.w,  y1 = Bv.x, z1 = Bv.y;
        float x2 = Bv.z, y2 = Bv.w, z2 = Cv.x;
        float x3 = Cv.y, y3 = Cv.z, z3 = Cv.w;
        spts[4 * tid + 0] = make_float4(x0, y0, z0, fmaf(x0, x0, fmaf(y0, y0, z0 * z0)));
        spts[4 * tid + 1] = make_float4(x1, y1, z1, fmaf(x1, x1, fmaf(y1, y1, z1 * z1)));
        spts[4 * tid + 2] = make_float4(x2, y2, z2, fmaf(x2, x2, fmaf(y2, y2, z2 * z2)));
        spts[4 * tid + 3] = make_float4(x3, y3, z3, fmaf(x3, x3, fmaf(y3, y3, z3 * z3)));
    }
    __syncthreads();

    const int lane = tid & 31, w = tid >> 5;
    const int n = blockIdx.x * 32 + w;          // query for this warp
    const float4 q = spts[n];                   // (broadcast read)

    float a;                                    // distributed ascending list
    int   il;

    // ---- init: bitonic KV sort (ascending) of the first 32 candidates ----
    {
        float4 p = spts[lane];
        float inner = fmaf(q.x, p.x, fmaf(q.y, p.y, q.z * p.z));
        a  = fmaf(-2.f, inner, q.w + p.w);
        il = lane;
#pragma unroll
        for (int k = 2; k <= 32; k <<= 1) {
#pragma unroll
            for (int j = k >> 1; j > 0; j >>= 1) {
                float ov = __shfl_xor_sync(0xffffffffu, a, j);
                int   oi = __shfl_xor_sync(0xffffffffu, il, j);
                bool keep_min = ((lane & k) == 0) == ((lane & j) == 0);
                bool take_own = keep_min ? (a <= ov) : (a >= ov);
                a  = take_own ? a  : ov;
                il = take_own ? il : oi;
            }
        }
    }
    float t = __shfl_sync(0xffffffffu, a, 15);

    // ---- scan remaining candidates ----
#pragma unroll 2
    for (int i = 1; i < N_ / 32; i++) {
        float4 p = spts[i * 32 + lane];
        float inner = fmaf(q.x, p.x, fmaf(q.y, p.y, q.z * p.z));
        float d = fmaf(-2.f, inner, q.w + p.w);
        unsigned mask = __ballot_sync(0xffffffffu, d < t);
        if (mask) {
            const int ibase = i * 32;
            do {
                const int src = __ffs(mask) - 1;
                mask &= mask - 1;
                const float dd = __shfl_sync(0xffffffffu, d, src);
                const int   jj = ibase + src;
                float au = __shfl_up_sync(0xffffffffu, a, 1);
                int   iu = __shfl_up_sync(0xffffffffu, il, 1);
                if (lane == 0) au = -CUDART_INF_F;
                const bool ins = dd < a;
                const float an = fminf(fmaxf(au, dd), a);
                il = !ins ? il : ((au <= dd) ? jj : iu);
                a = an;
            } while (mask);
            t = __shfl_sync(0xffffffffu, a, 15);
        }
    }

    if (lane < K_)
        g_idx[((size_t)b * N_ + n) * K_ + lane] = il;
}

// ---------------- K2: qt = X @ M + v, 4 rows per warp ------------------------
__global__ __launch_bounds__(1024) void qt_kernel(const float* __restrict__ X) {
    extern __shared__ float Ms[];               // 128*128 floats = 64KB
    for (int i = threadIdx.x; i < D_ * D_; i += 1024) Ms[i] = g_M[i];
    __syncthreads();

    const int warp = threadIdx.x >> 5, lane = threadIdx.x & 31;
    const int r0 = (blockIdx.x * 32 + warp) * 4;

    float xr[4][4];
#pragma unroll
    for (int r = 0; r < 4; r++)
#pragma unroll
        for (int t = 0; t < 4; t++)
            xr[r][t] = X[(size_t)(r0 + r) * D_ + lane + 32 * t];

    const float4* Ms4 = (const float4*)Ms;
    const float4 vinit = ((const float4*)g_v)[lane];
    float4 acc[4] = {vinit, vinit, vinit, vinit};

#pragma unroll
    for (int t = 0; t < 4; t++) {
#pragma unroll 4
        for (int l = 0; l < 32; l++) {
            float4 m = Ms4[(t * 32 + l) * 32 + lane];
#pragma unroll
            for (int r = 0; r < 4; r++) {
                float xc = __shfl_sync(0xffffffffu, xr[r][t], l);
                acc[r].x = fmaf(xc, m.x, acc[r].x);
                acc[r].y = fmaf(xc, m.y, acc[r].y);
                acc[r].z = fmaf(xc, m.z, acc[r].z);
                acc[r].w = fmaf(xc, m.w, acc[r].w);
            }
        }
    }
#pragma unroll
    for (int r = 0; r < 4; r++)
        ((float4*)g_qt)[(size_t)(r0 + r) * 32 + lane] = acc[r];
}

// ---------------- K3: transpose fp4_features [B,C,N] -> [B,N,C] fp16 ---------
__global__ void transpose_kernel(const float* __restrict__ F) {
    __shared__ float t[32][33];
    const int b = blockIdx.z;
    const int n0 = blockIdx.x * 32, c0 = blockIdx.y * 32;
    const int tx = threadIdx.x, ty = threadIdx.y;
    const float* Fb = F + (size_t)b * C_ * N_;
#pragma unroll
    for (int i = 0; i < 4; i++)
        t[ty + 8 * i][tx] = Fb[(size_t)(c0 + ty + 8 * i) * N_ + n0 + tx];
    __syncthreads();
    __half* Ftb = g_Ft + (size_t)b * N_ * C_;
#pragma unroll
    for (int i = 0; i < 4; i++)
        Ftb[(size_t)(n0 + ty + 8 * i) * C_ + c0 + tx] = __float2half(t[tx][ty + 8 * i]);
}

// ---------------- K3b: X (concat features) fp32 -> fp16 ----------------------
__global__ void xhalf_kernel(const float* __restrict__ X) {
    size_t i = (size_t)blockIdx.x * blockDim.x + threadIdx.x;  // one float4 each
    float4 v = ((const float4*)X)[i];
    __half2 a = __floats2half2_rn(v.x, v.y);
    __half2 b = __floats2half2_rn(v.z, v.w);
    uint2 u;
    u.x = *(const unsigned int*)&a;
    u.y = *(const unsigned int*)&b;
    ((uint2*)g_X16)[i] = u;
}

// ---------------- K4: scores + softmax + weighted gather + coalesced out -----
__global__ __launch_bounds__(1024) void attn_kernel(float* __restrict__ out) {
    __shared__ float tile[32 * 258];            // [point][channel], pad 258

    const int w = threadIdx.x >> 5, lane = threadIdx.x & 31;
    const int b = blockIdx.y;
    const int n0 = blockIdx.x * 32;
    const int n = n0 + w;
    const size_t pt = (size_t)b * N_ + n;

    const float4 q = ((const float4*)g_qt)[pt * 32 + lane];    // ch 4L..4L+3
    int jlane = (lane < K_) ? g_idx[pt * K_ + lane] : 0;

    // scores: s_k = qt . X16[j_k]  (row = 128 half = 32 uint2)
    const uint2* Xv = (const uint2*)g_X16 + (size_t)b * N_ * 32;
    float s[K_];
#pragma unroll
    for (int k = 0; k < K_; k++) {
        int j = __shfl_sync(0xffffffffu, jlane, k);
        uint2 xv = Xv[(size_t)j * 32 + lane];
        float2 f0 = __half22float2(*(const __half2*)&xv.x);
        float2 f1 = __half22float2(*(const __half2*)&xv.y);
        float p = fmaf(q.x, f0.x, fmaf(q.y, f0.y, fmaf(q.z, f1.x, q.w * f1.y)));
#pragma unroll
        for (int off = 16; off > 0; off >>= 1)
            p += __shfl_xor_sync(0xffffffffu, p, off);
        s[k] = p;
    }

    const float scale = 0.08838834764831845f;   // 1/sqrt(128)
    float m = s[0] * scale;
#pragma unroll
    for (int k = 1; k < K_; k++) m = fmaxf(m, s[k] * scale);
    float sum = 0.f;
#pragma unroll
    for (int k = 0; k < K_; k++) {
        s[k] = __expf(fmaf(s[k], scale, -m));
        sum += s[k];
    }
    const float inv = 1.f / sum;

    // weighted feature gather: Ft16 row = 256 half = 32 uint4; lane ch 8L..8L+7
    float a[8] = {0.f, 0.f, 0.f, 0.f, 0.f, 0.f, 0.f, 0.f};
    const uint4* Fv = (const uint4*)g_Ft + (size_t)b * N_ * 32;
#pragma unroll
    for (int k = 0; k < K_; k++) {
        int j = __shfl_sync(0xffffffffu, jlane, k);
        float ak = s[k] * inv;
        uint4 f = Fv[(size_t)j * 32 + lane];
        float2 p0 = __half22float2(*(const __half2*)&f.x);
        float2 p1 = __half22float2(*(const __half2*)&f.y);
        float2 p2 = __half22float2(*(const __half2*)&f.z);
        float2 p3 = __half22float2(*(const __half2*)&f.w);
        a[0] = fmaf(ak, p0.x, a[0]); a[1] = fmaf(ak, p0.y, a[1]);
        a[2] = fmaf(ak, p1.x, a[2]); a[3] = fmaf(ak, p1.y, a[3]);
        a[4] = fmaf(ak, p2.x, a[4]); a[5] = fmaf(ak, p2.y, a[5]);
        a[6] = fmaf(ak, p3.x, a[6]); a[7] = fmaf(ak, p3.y, a[7]);
    }

    // stage [point][channel]; float2 stores, reads are 2-way-conflict max
    float* trow = &tile[w * 258 + 8 * lane];
#pragma unroll
    for (int i = 0; i < 4; i++)
        ((float2*)trow)[i] = make_float2(a[2 * i], a[2 * i + 1]);
    __syncthreads();

    // coalesced write: lanes sweep n, rows sweep c
    float* ob = out + (size_t)b * C_ * N_;
#pragma unroll
    for (int r = 0; r < 8; r++) {
        int c = w + r * 32;
        ob[(size_t)c * N_ + n0 + lane] = tile[lane * 258 + c];
    }
}

// ---------------- launch ------------------------------------------------------
extern "C" void kernel_launch(void* const* d_in, const int* in_sizes, int n_in,
                              void* d_out, int out_size) {
    (void)in_sizes; (void)n_in; (void)out_size;
    const float* xyz = (const float*)d_in[0];   // [B,N,3]
    const float* F   = (const float*)d_in[1];   // [B,C,N]
    const float* X   = (const float*)d_in[2];   // [B,N,D]
    const float* Wq  = (const float*)d_in[3];
    const float* bq  = (const float*)d_in[4];
    const float* Wk  = (const float*)d_in[5];
    float* out = (float*)d_out;                 // [B,C,N]

    cudaFuncSetAttribute(knn_kernel, cudaFuncAttributeMaxDynamicSharedMemorySize, 65536);
    cudaFuncSetAttribute(qt_kernel,  cudaFuncAttributeMaxDynamicSharedMemorySize, 65536);

    fold_kernel<<<D_, D_>>>(Wq, Wk, bq);
    transpose_kernel<<<dim3(N_ / 32, C_ / 32, B_), dim3(32, 8)>>>(F);
    xhalf_kernel<<<(B_ * N_ * D_ / 4) / 256, 256>>>(X);
    knn_kernel<<<dim3(N_ / 32, B_), 1024, 65536>>>(xyz);
    qt_kernel<<<(B_ * N_) / 128, 1024, 65536>>>(X);
    attn_kernel<<<dim3(N_ / 32, B_), 1024>>>(out);
}